// round 1
// baseline (speedup 1.0000x reference)
#include <cuda_runtime.h>
#include <math.h>

// Problem constants
#define NN 50000
#define EE 800000
#define F_IN 512
#define HH 128
#define OD 3
#define CC 16
#define LD3H 384   // 3*H

// ---------------- device scratch (static, no allocations) ----------------
__device__ int   g_count[NN];
__device__ int   g_rowptr[NN + 1];
__device__ int   g_pos[NN];
__device__ int   g_bsum[64];
__device__ int   g_col[EE];
__device__ float g_val[EE];
__device__ float g_a1[(size_t)NN * LD3H];
__device__ float g_tmp[(size_t)NN * LD3H];
__device__ float g_g2[(size_t)NN * LD3H];

// ---------------- CSR build ----------------
__global__ void k_zero_counts() {
    int i = blockIdx.x * blockDim.x + threadIdx.x;
    if (i < NN) g_count[i] = 0;
}

__global__ void k_count(const int* __restrict__ idx) {
    int e = blockIdx.x * blockDim.x + threadIdx.x;
    if (e < EE) atomicAdd(&g_count[idx[e]], 1);
}

#define SCAN_B 1024
__global__ void k_scan1() {
    __shared__ int s[SCAN_B];
    int t = threadIdx.x;
    int i = blockIdx.x * SCAN_B + t;
    int v = (i < NN) ? g_count[i] : 0;
    s[t] = v;
    __syncthreads();
    #pragma unroll
    for (int o = 1; o < SCAN_B; o <<= 1) {
        int u = (t >= o) ? s[t - o] : 0;
        __syncthreads();
        s[t] += u;
        __syncthreads();
    }
    if (i < NN) g_rowptr[i] = s[t] - v;   // exclusive
    if (t == SCAN_B - 1) g_bsum[blockIdx.x] = s[t];
}

__global__ void k_scan2(int nblk) {
    if (threadIdx.x == 0) {
        int acc = 0;
        for (int b = 0; b < nblk; b++) { int u = g_bsum[b]; g_bsum[b] = acc; acc += u; }
    }
}

__global__ void k_scan3() {
    int i = blockIdx.x * SCAN_B + threadIdx.x;
    if (i < NN) {
        int v = g_rowptr[i] + g_bsum[blockIdx.x];
        g_rowptr[i] = v;
        g_pos[i] = v;
    }
    if (i == 0) g_rowptr[NN] = EE;
}

__global__ void k_scatter(const int* __restrict__ idx, const float* __restrict__ vals) {
    int e = blockIdx.x * blockDim.x + threadIdx.x;
    if (e < EE) {
        int r = idx[e];
        int p = atomicAdd(&g_pos[r], 1);
        g_col[p] = idx[EE + e];
        g_val[p] = vals[e];
    }
}

// ---------------- fp32 tiled GEMM: C[M,384] tile-n = A[M,K] @ B_nt[K,128] ----------------
// B_nt = Bbase + blockIdx.x * bstride, row-major ld=128 (w1/w2 natural layout).
#define BM 128
#define BN 128
#define BK 16

__global__ __launch_bounds__(256, 1)
void k_gemm(const float* __restrict__ A, int lda,
            const float* __restrict__ Bbase, int bstride,
            const float* __restrict__ bias,     // [3*128] or null
            float* __restrict__ C,              // ld = 384
            int M, int K, int do_relu)
{
    __shared__ float As[BK][BM];
    __shared__ float Bs[BK][BN];
    const float* B = Bbase + (size_t)blockIdx.x * bstride;
    const int m0 = blockIdx.y * BM;
    const int tid = threadIdx.x;
    const int tx = tid & 15;       // n-direction
    const int ty = tid >> 4;       // m-direction

    const int arow = tid >> 2;            // 0..63
    const int acol = (tid & 3) * 4;       // 0,4,8,12
    const int brow = tid >> 5;            // 0..7
    const int bcol = (tid & 31) * 4;      // 0..124

    float acc[8][8];
    #pragma unroll
    for (int i = 0; i < 8; i++)
        #pragma unroll
        for (int j = 0; j < 8; j++) acc[i][j] = 0.f;

    for (int k0 = 0; k0 < K; k0 += BK) {
        #pragma unroll
        for (int r = 0; r < 2; r++) {
            int row = arow + r * 64;
            int gr = m0 + row;
            float4 v = make_float4(0.f, 0.f, 0.f, 0.f);
            if (gr < M) v = *(const float4*)(A + (size_t)gr * lda + k0 + acol);
            As[acol + 0][row] = v.x;
            As[acol + 1][row] = v.y;
            As[acol + 2][row] = v.z;
            As[acol + 3][row] = v.w;
        }
        #pragma unroll
        for (int r = 0; r < 2; r++) {
            int row = brow + r * 8;
            float4 v = *(const float4*)(B + (size_t)(k0 + row) * 128 + bcol);
            *(float4*)&Bs[row][bcol] = v;
        }
        __syncthreads();

        #pragma unroll
        for (int kk = 0; kk < BK; kk++) {
            float af[8], bfv[8];
            #pragma unroll
            for (int i = 0; i < 8; i++) af[i] = As[kk][ty * 8 + i];
            #pragma unroll
            for (int j = 0; j < 8; j++) bfv[j] = Bs[kk][tx * 8 + j];
            #pragma unroll
            for (int i = 0; i < 8; i++)
                #pragma unroll
                for (int j = 0; j < 8; j++)
                    acc[i][j] = fmaf(af[i], bfv[j], acc[i][j]);
        }
        __syncthreads();
    }

    const int cb = blockIdx.x * BN;
    #pragma unroll
    for (int i = 0; i < 8; i++) {
        int gr = m0 + ty * 8 + i;
        if (gr >= M) continue;
        #pragma unroll
        for (int j = 0; j < 8; j += 4) {
            int c = tx * 8 + j;
            float4 v = make_float4(acc[i][j], acc[i][j + 1], acc[i][j + 2], acc[i][j + 3]);
            if (bias) {
                v.x += bias[cb + c];
                v.y += bias[cb + c + 1];
                v.z += bias[cb + c + 2];
                v.w += bias[cb + c + 3];
            }
            if (do_relu) {
                v.x = fmaxf(v.x, 0.f); v.y = fmaxf(v.y, 0.f);
                v.z = fmaxf(v.z, 0.f); v.w = fmaxf(v.w, 0.f);
            }
            *(float4*)(C + (size_t)gr * LD3H + cb + c) = v;
        }
    }
}

// ---------------- SpMM (CSR gather): one warp per row, 128 cols via float4 ----------------
__global__ void k_spmm128(const float* __restrict__ in, float* __restrict__ out)
{
    int warp = (blockIdx.x * blockDim.x + threadIdx.x) >> 5;
    int lane = threadIdx.x & 31;
    if (warp >= NN) return;
    int s = g_rowptr[warp];
    int e = g_rowptr[warp + 1];
    float4 acc = make_float4(0.f, 0.f, 0.f, 0.f);
    for (int p = s; p < e; p++) {
        int c = g_col[p];
        float v = g_val[p];
        float4 h = *(const float4*)(in + (size_t)c * LD3H + lane * 4);
        acc.x = fmaf(v, h.x, acc.x);
        acc.y = fmaf(v, h.y, acc.y);
        acc.z = fmaf(v, h.z, acc.z);
        acc.w = fmaf(v, h.w, acc.w);
    }
    *(float4*)(out + (size_t)warp * LD3H + lane * 4) = acc;
}

// copy a 128-col block (ld 384)
__global__ void k_copy128(const float* __restrict__ in, float* __restrict__ out)
{
    int idx = blockIdx.x * blockDim.x + threadIdx.x;  // over NN*32 float4
    if (idx >= NN * 32) return;
    int r = idx >> 5, c = idx & 31;
    ((float4*)(out + (size_t)r * LD3H))[c] = ((const float4*)(in + (size_t)r * LD3H))[c];
}

// ---------------- final: out = log_softmax((g + b2cat) @ wf + bf) ----------------
#define FROWS 8
__global__ __launch_bounds__(128)
void k_final(const float* __restrict__ g,
             const float* __restrict__ b2,   // [3*128] == b2cat
             const float* __restrict__ wf,   // [384*16]
             const float* __restrict__ bfv,  // [16]
             float* __restrict__ out)
{
    __shared__ float wfs[LD3H * CC];
    __shared__ float gs[FROWS][LD3H];
    int tid = threadIdx.x;  // 128
    for (int i = tid; i < LD3H * CC; i += 128) wfs[i] = wf[i];
    int row0 = blockIdx.x * FROWS;
    for (int i = tid; i < FROWS * LD3H; i += 128) {
        int r = i / LD3H, k = i % LD3H;
        int gr = row0 + r;
        gs[r][k] = (gr < NN) ? g[(size_t)gr * LD3H + k] + b2[k] : 0.f;
    }
    __syncthreads();

    int r = tid >> 4;        // 0..7
    int c = tid & 15;        // class
    float acc = bfv[c];
    #pragma unroll 8
    for (int k = 0; k < LD3H; k++) acc = fmaf(gs[r][k], wfs[k * CC + c], acc);

    // log-softmax across the 16-lane class group
    float m = acc;
    #pragma unroll
    for (int o = 8; o >= 1; o >>= 1) m = fmaxf(m, __shfl_xor_sync(0xffffffffu, m, o, 16));
    float ex = __expf(acc - m);
    float s = ex;
    #pragma unroll
    for (int o = 8; o >= 1; o >>= 1) s += __shfl_xor_sync(0xffffffffu, s, o, 16);
    int gr = row0 + r;
    if (gr < NN) out[gr * CC + c] = acc - m - logf(s);
}

// ---------------- launch ----------------
extern "C" void kernel_launch(void* const* d_in, const int* in_sizes, int n_in,
                              void* d_out, int out_size)
{
    const float* x   = (const float*)d_in[0];
    const int*   adj = (const int*)d_in[1];
    const float* av  = (const float*)d_in[2];
    const float* w1  = (const float*)d_in[3];
    const float* b1  = (const float*)d_in[4];
    const float* w2  = (const float*)d_in[5];
    const float* b2  = (const float*)d_in[6];
    const float* wf  = (const float*)d_in[7];
    const float* bf  = (const float*)d_in[8];
    float* out = (float*)d_out;

    float *a1, *tmp, *g2;
    cudaGetSymbolAddress((void**)&a1,  g_a1);
    cudaGetSymbolAddress((void**)&tmp, g_tmp);
    cudaGetSymbolAddress((void**)&g2,  g_g2);

    const int nscan = (NN + SCAN_B - 1) / SCAN_B;  // 49

    // CSR build (rebuilt every launch; deterministic)
    k_zero_counts<<<(NN + 255) / 256, 256>>>();
    k_count<<<(EE + 255) / 256, 256>>>(adj);
    k_scan1<<<nscan, SCAN_B>>>();
    k_scan2<<<1, 32>>>(nscan);
    k_scan3<<<nscan, SCAN_B>>>();
    k_scatter<<<(EE + 255) / 256, 256>>>(adj, av);

    dim3 ggrid(3, (NN + BM - 1) / BM);

    // Stage 1: a1 = relu(x @ W1cat + b1cat), then hop blocks 1 (x1) and 2 (x2)
    k_gemm<<<ggrid, 256>>>(x, F_IN, w1, F_IN * HH, b1, a1, NN, F_IN, 1);

    const int sgrid = (NN * 32 + 127) / 128;   // warps = NN, 4 warps/block
    k_spmm128<<<(NN + 3) / 4, 128>>>(a1 + HH,     tmp + HH);
    k_spmm128<<<(NN + 3) / 4, 128>>>(a1 + 2 * HH, tmp + 2 * HH);
    k_spmm128<<<(NN + 3) / 4, 128>>>(tmp + 2 * HH, a1 + 2 * HH);
    k_copy128<<<(NN * 32 + 255) / 256, 256>>>(tmp + HH, a1 + HH);

    // Stage 2: g2 = a1 @ W2cat (bias deferred), then hop blocks 1 and 2
    k_gemm<<<ggrid, 256>>>(a1, LD3H, w2, LD3H * HH, (const float*)0, g2, NN, LD3H, 0);

    k_spmm128<<<(NN + 3) / 4, 128>>>(g2 + HH,      tmp + HH);
    k_spmm128<<<(NN + 3) / 4, 128>>>(g2 + 2 * HH,  tmp + 2 * HH);
    k_spmm128<<<(NN + 3) / 4, 128>>>(tmp + 2 * HH, g2 + 2 * HH);
    k_copy128<<<(NN * 32 + 255) / 256, 256>>>(tmp + HH, g2 + HH);

    // Final: log_softmax((g2 + b2cat) @ wf + bf)
    k_final<<<(NN + FROWS - 1) / FROWS, 128>>>(g2, b2, wf, bf, out);

    (void)in_sizes; (void)n_in; (void)out_size; (void)sgrid;
}

// round 2
// speedup vs baseline: 1.8918x; 1.8918x over previous
#include <cuda_runtime.h>
#include <math.h>
#include <stdint.h>

// Problem constants
#define NN 50000
#define EE 800000
#define F_IN 512
#define HH 128
#define CC 16
#define LD3H 384   // 3*H

// ---------------- device scratch (static, no allocations) ----------------
__device__ int   g_count[NN];
__device__ int   g_rowptr[NN + 1];
__device__ int   g_pos[NN];
__device__ int   g_bsum[64];
__device__ int   g_col[EE];
__device__ float g_val[EE];
__device__ float g_bufA[(size_t)NN * LD3H];
__device__ float g_bufB[(size_t)NN * LD3H];
__device__ float g_bufC[(size_t)NN * LD3H];

// ---------------- CSR build ----------------
__global__ void k_zero_counts() {
    int i = blockIdx.x * blockDim.x + threadIdx.x;
    if (i < NN) g_count[i] = 0;
}

__global__ void k_count(const int* __restrict__ idx) {
    int e = blockIdx.x * blockDim.x + threadIdx.x;
    if (e < EE) atomicAdd(&g_count[idx[e]], 1);
}

#define SCAN_B 1024
__global__ void k_scan1() {
    __shared__ int s[SCAN_B];
    int t = threadIdx.x;
    int i = blockIdx.x * SCAN_B + t;
    int v = (i < NN) ? g_count[i] : 0;
    s[t] = v;
    __syncthreads();
    #pragma unroll
    for (int o = 1; o < SCAN_B; o <<= 1) {
        int u = (t >= o) ? s[t - o] : 0;
        __syncthreads();
        s[t] += u;
        __syncthreads();
    }
    if (i < NN) g_rowptr[i] = s[t] - v;   // exclusive
    if (t == SCAN_B - 1) g_bsum[blockIdx.x] = s[t];
}

__global__ void k_scan2(int nblk) {
    // single-warp shfl scan over block sums
    int lane = threadIdx.x;
    int carry = 0;
    for (int base = 0; base < nblk; base += 32) {
        int i = base + lane;
        int v = (i < nblk) ? g_bsum[i] : 0;
        int incl = v;
        #pragma unroll
        for (int o = 1; o < 32; o <<= 1) {
            int u = __shfl_up_sync(0xffffffffu, incl, o);
            if (lane >= o) incl += u;
        }
        if (i < nblk) g_bsum[i] = carry + incl - v;   // exclusive
        carry += __shfl_sync(0xffffffffu, incl, 31);
    }
}

__global__ void k_scan3() {
    int i = blockIdx.x * SCAN_B + threadIdx.x;
    if (i < NN) {
        int v = g_rowptr[i] + g_bsum[blockIdx.x];
        g_rowptr[i] = v;
        g_pos[i] = v;
    }
    if (i == 0) g_rowptr[NN] = EE;
}

__global__ void k_scatter(const int* __restrict__ idx, const float* __restrict__ vals) {
    int e = blockIdx.x * blockDim.x + threadIdx.x;
    if (e < EE) {
        int r = idx[e];
        int p = atomicAdd(&g_pos[r], 1);
        g_col[p] = idx[EE + e];
        g_val[p] = vals[e];
    }
}

// ---------------- tf32 tensor-core GEMM ----------------
// C_nblock[M,128] = A[M,K] @ B_nblock[K,128]   (B_nblock = Bbase + blockIdx.x*bstride)
// Block tile 128x128xK, BK=32, 8 warps, warp tile 64x32 (4x4 m16n8k8 per k-step).

__device__ __forceinline__ uint32_t f2tf(float f) {
    uint32_t u; asm("cvt.rna.tf32.f32 %0, %1;" : "=r"(u) : "f"(f)); return u;
}

__device__ __forceinline__ void mma_tf32(float* c, const uint32_t* a, const uint32_t* b) {
    asm volatile(
        "mma.sync.aligned.m16n8k8.row.col.f32.tf32.tf32.f32 "
        "{%0,%1,%2,%3}, {%4,%5,%6,%7}, {%8,%9}, {%0,%1,%2,%3};\n"
        : "+f"(c[0]), "+f"(c[1]), "+f"(c[2]), "+f"(c[3])
        : "r"(a[0]), "r"(a[1]), "r"(a[2]), "r"(a[3]), "r"(b[0]), "r"(b[1]));
}

#define LDA_S 36    // A smem row stride (words): bank = (4m + k) mod 32, conflict-free
#define LDB_S 136   // B smem row stride (words): bank = (8k + n) mod 32, conflict-free

__global__ __launch_bounds__(256, 2)
void k_gemm_tc(const float* __restrict__ A, int lda,
               const float* __restrict__ Bbase, int bstride,
               const float* __restrict__ bias,      // [3*128] or null
               float* __restrict__ C0, float* __restrict__ C1, float* __restrict__ C2,
               int M, int K, int do_relu)
{
    __shared__ uint32_t As[128][LDA_S];
    __shared__ uint32_t Bs[32][LDB_S];

    const float* B = Bbase + (size_t)blockIdx.x * bstride;
    float* C = (blockIdx.x == 0) ? C0 : ((blockIdx.x == 1) ? C1 : C2);
    const float* bi = bias ? (bias + blockIdx.x * 128) : (const float*)0;

    const int m0   = blockIdx.y * 128;
    const int tid  = threadIdx.x;
    const int lane = tid & 31;
    const int wid  = tid >> 5;
    const int wm0  = (wid & 1) * 64;
    const int wn0  = (wid >> 1) * 32;
    const int gp   = lane >> 2;   // group id 0..7
    const int tg   = lane & 3;    // thread-in-group 0..3

    float acc[4][4][4];
    #pragma unroll
    for (int i = 0; i < 4; i++)
        #pragma unroll
        for (int j = 0; j < 4; j++)
            #pragma unroll
            for (int q = 0; q < 4; q++) acc[i][j][q] = 0.f;

    for (int k0 = 0; k0 < K; k0 += 32) {
        // stage A tile 128x32 (convert fp32->tf32 rna)
        #pragma unroll
        for (int s = 0; s < 4; s++) {
            int idx = s * 256 + tid;
            int r = idx >> 3;
            int c = (idx & 7) * 4;
            int gr = m0 + r;
            float4 v = make_float4(0.f, 0.f, 0.f, 0.f);
            if (gr < M) v = *(const float4*)(A + (size_t)gr * lda + k0 + c);
            uint4 u = make_uint4(f2tf(v.x), f2tf(v.y), f2tf(v.z), f2tf(v.w));
            *(uint4*)&As[r][c] = u;
        }
        // stage B tile 32x128
        #pragma unroll
        for (int s = 0; s < 4; s++) {
            int idx = s * 256 + tid;
            int r = idx >> 5;
            int c = (idx & 31) * 4;
            float4 v = *(const float4*)(B + (size_t)(k0 + r) * 128 + c);
            uint4 u = make_uint4(f2tf(v.x), f2tf(v.y), f2tf(v.z), f2tf(v.w));
            *(uint4*)&Bs[r][c] = u;
        }
        __syncthreads();

        #pragma unroll
        for (int ks = 0; ks < 4; ks++) {
            uint32_t af[4][4], bf[4][2];
            #pragma unroll
            for (int i = 0; i < 4; i++) {
                int r = wm0 + i * 16 + gp;
                int kk = ks * 8 + tg;
                af[i][0] = As[r][kk];
                af[i][1] = As[r + 8][kk];
                af[i][2] = As[r][kk + 4];
                af[i][3] = As[r + 8][kk + 4];
            }
            #pragma unroll
            for (int j = 0; j < 4; j++) {
                int n = wn0 + j * 8 + gp;
                int kk = ks * 8 + tg;
                bf[j][0] = Bs[kk][n];
                bf[j][1] = Bs[kk + 4][n];
            }
            #pragma unroll
            for (int i = 0; i < 4; i++)
                #pragma unroll
                for (int j = 0; j < 4; j++)
                    mma_tf32(acc[i][j], af[i], bf[j]);
        }
        __syncthreads();
    }

    // epilogue: C row-major ld=384, pointer already offset to this n-block
    #pragma unroll
    for (int i = 0; i < 4; i++) {
        #pragma unroll
        for (int rr = 0; rr < 2; rr++) {
            int row = m0 + wm0 + i * 16 + gp + rr * 8;
            if (row >= M) continue;
            #pragma unroll
            for (int j = 0; j < 4; j++) {
                int col = wn0 + j * 8 + 2 * tg;
                float2 v;
                v.x = acc[i][j][rr * 2 + 0];
                v.y = acc[i][j][rr * 2 + 1];
                if (bi) { v.x += bi[col]; v.y += bi[col + 1]; }
                if (do_relu) { v.x = fmaxf(v.x, 0.f); v.y = fmaxf(v.y, 0.f); }
                *(float2*)(C + (size_t)row * LD3H + col) = v;
            }
        }
    }
}

// ---------------- SpMM (CSR gather) ----------------
// 256-wide: one warp per row, 2 float4 per lane; dual destinations.
__global__ void k_spmm256(const float* __restrict__ src,
                          float* __restrict__ dstA, float* __restrict__ dstB)
{
    int warp = (blockIdx.x * blockDim.x + threadIdx.x) >> 5;
    int lane = threadIdx.x & 31;
    if (warp >= NN) return;
    int s = g_rowptr[warp];
    int e = g_rowptr[warp + 1];
    float4 a0 = make_float4(0.f, 0.f, 0.f, 0.f);
    float4 a1 = make_float4(0.f, 0.f, 0.f, 0.f);
    int p = s;
    for (; p + 1 < e; p += 2) {
        int   c0 = g_col[p],   c1 = g_col[p + 1];
        float v0 = g_val[p],   v1 = g_val[p + 1];
        const float* r0 = src + (size_t)c0 * LD3H + lane * 4;
        const float* r1 = src + (size_t)c1 * LD3H + lane * 4;
        float4 h0 = *(const float4*)r0;
        float4 h1 = *(const float4*)(r0 + 128);
        float4 g0 = *(const float4*)r1;
        float4 g1 = *(const float4*)(r1 + 128);
        a0.x = fmaf(v0, h0.x, a0.x); a0.y = fmaf(v0, h0.y, a0.y);
        a0.z = fmaf(v0, h0.z, a0.z); a0.w = fmaf(v0, h0.w, a0.w);
        a1.x = fmaf(v0, h1.x, a1.x); a1.y = fmaf(v0, h1.y, a1.y);
        a1.z = fmaf(v0, h1.z, a1.z); a1.w = fmaf(v0, h1.w, a1.w);
        a0.x = fmaf(v1, g0.x, a0.x); a0.y = fmaf(v1, g0.y, a0.y);
        a0.z = fmaf(v1, g0.z, a0.z); a0.w = fmaf(v1, g0.w, a0.w);
        a1.x = fmaf(v1, g1.x, a1.x); a1.y = fmaf(v1, g1.y, a1.y);
        a1.z = fmaf(v1, g1.z, a1.z); a1.w = fmaf(v1, g1.w, a1.w);
    }
    if (p < e) {
        int c0 = g_col[p];
        float v0 = g_val[p];
        const float* r0 = src + (size_t)c0 * LD3H + lane * 4;
        float4 h0 = *(const float4*)r0;
        float4 h1 = *(const float4*)(r0 + 128);
        a0.x = fmaf(v0, h0.x, a0.x); a0.y = fmaf(v0, h0.y, a0.y);
        a0.z = fmaf(v0, h0.z, a0.z); a0.w = fmaf(v0, h0.w, a0.w);
        a1.x = fmaf(v0, h1.x, a1.x); a1.y = fmaf(v0, h1.y, a1.y);
        a1.z = fmaf(v0, h1.z, a1.z); a1.w = fmaf(v0, h1.w, a1.w);
    }
    *(float4*)(dstA + (size_t)warp * LD3H + lane * 4) = a0;
    *(float4*)(dstB + (size_t)warp * LD3H + lane * 4) = a1;
}

// 128-wide single-destination
__global__ void k_spmm128(const float* __restrict__ src, float* __restrict__ dst)
{
    int warp = (blockIdx.x * blockDim.x + threadIdx.x) >> 5;
    int lane = threadIdx.x & 31;
    if (warp >= NN) return;
    int s = g_rowptr[warp];
    int e = g_rowptr[warp + 1];
    float4 a0 = make_float4(0.f, 0.f, 0.f, 0.f);
    int p = s;
    for (; p + 1 < e; p += 2) {
        int   c0 = g_col[p],   c1 = g_col[p + 1];
        float v0 = g_val[p],   v1 = g_val[p + 1];
        float4 h0 = *(const float4*)(src + (size_t)c0 * LD3H + lane * 4);
        float4 h1 = *(const float4*)(src + (size_t)c1 * LD3H + lane * 4);
        a0.x = fmaf(v0, h0.x, a0.x); a0.y = fmaf(v0, h0.y, a0.y);
        a0.z = fmaf(v0, h0.z, a0.z); a0.w = fmaf(v0, h0.w, a0.w);
        a0.x = fmaf(v1, h1.x, a0.x); a0.y = fmaf(v1, h1.y, a0.y);
        a0.z = fmaf(v1, h1.z, a0.z); a0.w = fmaf(v1, h1.w, a0.w);
    }
    if (p < e) {
        int c0 = g_col[p];
        float v0 = g_val[p];
        float4 h0 = *(const float4*)(src + (size_t)c0 * LD3H + lane * 4);
        a0.x = fmaf(v0, h0.x, a0.x); a0.y = fmaf(v0, h0.y, a0.y);
        a0.z = fmaf(v0, h0.z, a0.z); a0.w = fmaf(v0, h0.w, a0.w);
    }
    *(float4*)(dst + (size_t)warp * LD3H + lane * 4) = a0;
}

// ---------------- final: out = log_softmax((g + b2cat) @ wf + bf) ----------------
#define FROWS 8
__global__ __launch_bounds__(128)
void k_final(const float* __restrict__ g,
             const float* __restrict__ b2,   // [3*128]
             const float* __restrict__ wf,   // [384*16]
             const float* __restrict__ bfv,  // [16]
             float* __restrict__ out)
{
    __shared__ float wfs[LD3H * CC];
    __shared__ float gs[FROWS][LD3H];
    int tid = threadIdx.x;  // 128
    for (int i = tid; i < LD3H * CC; i += 128) wfs[i] = wf[i];
    int row0 = blockIdx.x * FROWS;
    for (int i = tid; i < FROWS * LD3H; i += 128) {
        int r = i / LD3H, k = i % LD3H;
        int gr = row0 + r;
        gs[r][k] = (gr < NN) ? g[(size_t)gr * LD3H + k] + b2[k] : 0.f;
    }
    __syncthreads();

    int r = tid >> 4;        // 0..7
    int c = tid & 15;        // class
    float acc = bfv[c];
    #pragma unroll 8
    for (int k = 0; k < LD3H; k++) acc = fmaf(gs[r][k], wfs[k * CC + c], acc);

    float m = acc;
    #pragma unroll
    for (int o = 8; o >= 1; o >>= 1) m = fmaxf(m, __shfl_xor_sync(0xffffffffu, m, o, 16));
    float ex = __expf(acc - m);
    float s = ex;
    #pragma unroll
    for (int o = 8; o >= 1; o >>= 1) s += __shfl_xor_sync(0xffffffffu, s, o, 16);
    int gr = row0 + r;
    if (gr < NN) out[gr * CC + c] = acc - m - logf(s);
}

// ---------------- launch ----------------
extern "C" void kernel_launch(void* const* d_in, const int* in_sizes, int n_in,
                              void* d_out, int out_size)
{
    const float* x   = (const float*)d_in[0];
    const int*   adj = (const int*)d_in[1];
    const float* av  = (const float*)d_in[2];
    const float* w1  = (const float*)d_in[3];
    const float* b1  = (const float*)d_in[4];
    const float* w2  = (const float*)d_in[5];
    const float* b2  = (const float*)d_in[6];
    const float* wf  = (const float*)d_in[7];
    const float* bf  = (const float*)d_in[8];
    float* out = (float*)d_out;

    float *bufA, *bufB, *bufC;
    cudaGetSymbolAddress((void**)&bufA, g_bufA);
    cudaGetSymbolAddress((void**)&bufB, g_bufB);
    cudaGetSymbolAddress((void**)&bufC, g_bufC);

    const int nscan = (NN + SCAN_B - 1) / SCAN_B;  // 49

    // CSR build
    k_zero_counts<<<(NN + 255) / 256, 256>>>();
    k_count<<<(EE + 255) / 256, 256>>>(adj);
    k_scan1<<<nscan, SCAN_B>>>();
    k_scan2<<<1, 32>>>(nscan);
    k_scan3<<<nscan, SCAN_B>>>();
    k_scatter<<<(EE + 255) / 256, 256>>>(adj, av);

    dim3 ggrid(3, (NN + 127) / 128);
    const int sblocks = (NN + 3) / 4;   // 4 warps/block, 128 threads

    // Stage 1: relu(x @ W1cat + b1cat); block0 -> bufA, blocks1,2 staged in bufB
    k_gemm_tc<<<ggrid, 256>>>(x, F_IN, w1, F_IN * HH, b1,
                              bufA, bufB + HH, bufB + 2 * HH, NN, F_IN, 1);
    // hop1 of blocks 1&2 (256-wide); hop2 of block2
    k_spmm256<<<sblocks, 128>>>(bufB + HH, bufA + HH, bufC + 2 * HH);
    k_spmm128<<<sblocks, 128>>>(bufC + 2 * HH, bufA + 2 * HH);

    // Stage 2: bufA @ W2cat (bias deferred); block0 -> bufC, blocks1,2 staged in bufB
    k_gemm_tc<<<ggrid, 256>>>(bufA, LD3H, w2, LD3H * HH, (const float*)0,
                              bufC, bufB + HH, bufB + 2 * HH, NN, LD3H, 0);
    k_spmm256<<<sblocks, 128>>>(bufB + HH, bufC + HH, bufA + 2 * HH);
    k_spmm128<<<sblocks, 128>>>(bufA + 2 * HH, bufC + 2 * HH);

    // Final
    k_final<<<(NN + FROWS - 1) / FROWS, 128>>>(bufC, b2, wf, bf, out);

    (void)in_sizes; (void)n_in; (void)out_size;
}

// round 3
// speedup vs baseline: 1.9587x; 1.0353x over previous
#include <cuda_runtime.h>
#include <math.h>
#include <stdint.h>

// Problem constants
#define NN 50000
#define EE 800000
#define F_IN 512
#define HH 128
#define CC 16
#define LD3H 384   // 3*H

// ---------------- device scratch (static, no allocations) ----------------
__device__ int   g_count[NN];
__device__ int   g_rowptr[NN + 1];
__device__ int   g_pos[NN];
__device__ int   g_bsum[64];
__device__ int   g_col[EE];
__device__ float g_val[EE];
__device__ float g_bufA[(size_t)NN * LD3H];
__device__ float g_bufB[(size_t)NN * LD3H];
__device__ float g_bufC[(size_t)NN * LD3H];

// ---------------- CSR build ----------------
__global__ void k_zero_counts() {
    int i = blockIdx.x * blockDim.x + threadIdx.x;
    if (i < NN) g_count[i] = 0;
}

__global__ void k_count(const int* __restrict__ idx) {
    int e = blockIdx.x * blockDim.x + threadIdx.x;
    if (e < EE) atomicAdd(&g_count[idx[e]], 1);
}

#define SCAN_B 1024
__global__ void k_scan1() {
    __shared__ int s[SCAN_B];
    int t = threadIdx.x;
    int i = blockIdx.x * SCAN_B + t;
    int v = (i < NN) ? g_count[i] : 0;
    s[t] = v;
    __syncthreads();
    #pragma unroll
    for (int o = 1; o < SCAN_B; o <<= 1) {
        int u = (t >= o) ? s[t - o] : 0;
        __syncthreads();
        s[t] += u;
        __syncthreads();
    }
    if (i < NN) g_rowptr[i] = s[t] - v;   // exclusive
    if (t == SCAN_B - 1) g_bsum[blockIdx.x] = s[t];
}

__global__ void k_scan2(int nblk) {
    int lane = threadIdx.x;
    int carry = 0;
    for (int base = 0; base < nblk; base += 32) {
        int i = base + lane;
        int v = (i < nblk) ? g_bsum[i] : 0;
        int incl = v;
        #pragma unroll
        for (int o = 1; o < 32; o <<= 1) {
            int u = __shfl_up_sync(0xffffffffu, incl, o);
            if (lane >= o) incl += u;
        }
        if (i < nblk) g_bsum[i] = carry + incl - v;   // exclusive
        carry += __shfl_sync(0xffffffffu, incl, 31);
    }
}

__global__ void k_scan3() {
    int i = blockIdx.x * SCAN_B + threadIdx.x;
    if (i < NN) {
        int v = g_rowptr[i] + g_bsum[blockIdx.x];
        g_rowptr[i] = v;
        g_pos[i] = v;
    }
    if (i == 0) g_rowptr[NN] = EE;
}

__global__ void k_scatter(const int* __restrict__ idx, const float* __restrict__ vals) {
    int e = blockIdx.x * blockDim.x + threadIdx.x;
    if (e < EE) {
        int r = idx[e];
        int p = atomicAdd(&g_pos[r], 1);
        g_col[p] = idx[EE + e];
        g_val[p] = vals[e];
    }
}

// ---------------- tf32 tensor-core GEMM, cp.async double-buffered ----------------
// C_nblock[M,128] = A[M,K] @ B_nblock[K,128]   (B_nblock = Bbase + blockIdx.x*bstride)
// Block tile 128x128, BK=32, 8 warps, warp tile 64x32 (4x4 m16n8k8 per k-step).

__device__ __forceinline__ uint32_t f2tf(float f) {
    uint32_t u; asm("cvt.rna.tf32.f32 %0, %1;" : "=r"(u) : "f"(f)); return u;
}

__device__ __forceinline__ void mma_tf32(float* c, const uint32_t* a, const uint32_t* b) {
    asm volatile(
        "mma.sync.aligned.m16n8k8.row.col.f32.tf32.tf32.f32 "
        "{%0,%1,%2,%3}, {%4,%5,%6,%7}, {%8,%9}, {%0,%1,%2,%3};\n"
        : "+f"(c[0]), "+f"(c[1]), "+f"(c[2]), "+f"(c[3])
        : "r"(a[0]), "r"(a[1]), "r"(a[2]), "r"(a[3]), "r"(b[0]), "r"(b[1]));
}

__device__ __forceinline__ void cpa16(uint32_t dst_smem, const void* src, int valid) {
    asm volatile("cp.async.cg.shared.global [%0], [%1], 16, %2;\n"
                 :: "r"(dst_smem), "l"(src), "r"(valid ? 16 : 0));
}
__device__ __forceinline__ void cpa_commit() { asm volatile("cp.async.commit_group;\n"); }
__device__ __forceinline__ void cpa_wait0()  { asm volatile("cp.async.wait_group 0;\n"); }

#define LDA_S 36    // A smem row stride (words): conflict-free, 144B (16B-aligned)
#define LDB_S 136   // B smem row stride (words): conflict-free, 544B (16B-aligned)
#define A_BUF_W (128 * LDA_S)
#define B_BUF_W (32 * LDB_S)
#define GEMM_SMEM_BYTES ((2 * A_BUF_W + 2 * B_BUF_W) * 4)

__global__ __launch_bounds__(256, 2)
void k_gemm_tc(const float* __restrict__ A, int lda,
               const float* __restrict__ Bbase, int bstride,
               const float* __restrict__ bias,      // [3*128] or null
               float* __restrict__ C0, float* __restrict__ C1, float* __restrict__ C2,
               int M, int K, int do_relu)
{
    extern __shared__ uint32_t smem[];
    uint32_t* As = smem;                       // [2][128][LDA_S], raw fp32 bits
    uint32_t* Bs = smem + 2 * A_BUF_W;         // [2][32][LDB_S]

    const float* B = Bbase + (size_t)blockIdx.x * bstride;
    float* C = (blockIdx.x == 0) ? C0 : ((blockIdx.x == 1) ? C1 : C2);
    const float* bi = bias ? (bias + blockIdx.x * 128) : (const float*)0;

    const int m0   = blockIdx.y * 128;
    const int tid  = threadIdx.x;
    const int lane = tid & 31;
    const int wid  = tid >> 5;
    const int wm0  = (wid & 1) * 64;
    const int wn0  = (wid >> 1) * 32;
    const int gp   = lane >> 2;   // 0..7
    const int tg   = lane & 3;    // 0..3

    // per-thread staging coordinates
    const int ar = tid >> 1;             // A row handled twice? -> see loop: 4 chunks of 256 thr
    (void)ar;

    float acc[4][4][4];
    #pragma unroll
    for (int i = 0; i < 4; i++)
        #pragma unroll
        for (int j = 0; j < 4; j++)
            #pragma unroll
            for (int q = 0; q < 4; q++) acc[i][j][q] = 0.f;

    const int nk = K >> 5;   // k-iterations of 32

    // stage k-tile kt into buffer buf
    auto stage = [&](int kt, int buf) {
        const int k0 = kt << 5;
        uint32_t abase = (uint32_t)__cvta_generic_to_shared(As + buf * A_BUF_W);
        uint32_t bbase = (uint32_t)__cvta_generic_to_shared(Bs + buf * B_BUF_W);
        #pragma unroll
        for (int s = 0; s < 4; s++) {
            int idx = s * 256 + tid;
            int r = idx >> 3;
            int c = (idx & 7) * 4;
            int gr = m0 + r;
            int ok = gr < M;
            int srow = ok ? gr : (M - 1);
            cpa16(abase + (r * LDA_S + c) * 4, A + (size_t)srow * lda + k0 + c, ok);
        }
        #pragma unroll
        for (int s = 0; s < 4; s++) {
            int idx = s * 256 + tid;
            int r = idx >> 5;
            int c = (idx & 31) * 4;
            cpa16(bbase + (r * LDB_S + c) * 4, B + (size_t)(k0 + r) * 128 + c, 1);
        }
        cpa_commit();
    };

    stage(0, 0);

    for (int kt = 0; kt < nk; kt++) {
        cpa_wait0();
        __syncthreads();
        if (kt + 1 < nk) stage(kt + 1, (kt + 1) & 1);

        const uint32_t* Ab = As + (kt & 1) * A_BUF_W;
        const uint32_t* Bb = Bs + (kt & 1) * B_BUF_W;

        #pragma unroll
        for (int ks = 0; ks < 4; ks++) {
            uint32_t af[4][4], bf[4][2];
            const int kk = ks * 8 + tg;
            #pragma unroll
            for (int i = 0; i < 4; i++) {
                int r = wm0 + i * 16 + gp;
                af[i][0] = f2tf(__uint_as_float(Ab[r * LDA_S + kk]));
                af[i][1] = f2tf(__uint_as_float(Ab[(r + 8) * LDA_S + kk]));
                af[i][2] = f2tf(__uint_as_float(Ab[r * LDA_S + kk + 4]));
                af[i][3] = f2tf(__uint_as_float(Ab[(r + 8) * LDA_S + kk + 4]));
            }
            #pragma unroll
            for (int j = 0; j < 4; j++) {
                int n = wn0 + j * 8 + gp;
                bf[j][0] = f2tf(__uint_as_float(Bb[kk * LDB_S + n]));
                bf[j][1] = f2tf(__uint_as_float(Bb[(kk + 4) * LDB_S + n]));
            }
            #pragma unroll
            for (int i = 0; i < 4; i++)
                #pragma unroll
                for (int j = 0; j < 4; j++)
                    mma_tf32(acc[i][j], af[i], bf[j]);
        }
        __syncthreads();
    }

    // epilogue: C row-major ld=384, pointer already offset to this n-block
    #pragma unroll
    for (int i = 0; i < 4; i++) {
        #pragma unroll
        for (int rr = 0; rr < 2; rr++) {
            int row = m0 + wm0 + i * 16 + gp + rr * 8;
            if (row >= M) continue;
            #pragma unroll
            for (int j = 0; j < 4; j++) {
                int col = wn0 + j * 8 + 2 * tg;
                float2 v;
                v.x = acc[i][j][rr * 2 + 0];
                v.y = acc[i][j][rr * 2 + 1];
                if (bi) { v.x += bi[col]; v.y += bi[col + 1]; }
                if (do_relu) { v.x = fmaxf(v.x, 0.f); v.y = fmaxf(v.y, 0.f); }
                *(float2*)(C + (size_t)row * LD3H + col) = v;
            }
        }
    }
}

// ---------------- SpMM (CSR gather) ----------------
__global__ void k_spmm256(const float* __restrict__ src,
                          float* __restrict__ dstA, float* __restrict__ dstB)
{
    int warp = (blockIdx.x * blockDim.x + threadIdx.x) >> 5;
    int lane = threadIdx.x & 31;
    if (warp >= NN) return;
    int s = g_rowptr[warp];
    int e = g_rowptr[warp + 1];
    float4 a0 = make_float4(0.f, 0.f, 0.f, 0.f);
    float4 a1 = make_float4(0.f, 0.f, 0.f, 0.f);
    int p = s;
    for (; p + 1 < e; p += 2) {
        int   c0 = g_col[p],   c1 = g_col[p + 1];
        float v0 = g_val[p],   v1 = g_val[p + 1];
        const float* r0 = src + (size_t)c0 * LD3H + lane * 4;
        const float* r1 = src + (size_t)c1 * LD3H + lane * 4;
        float4 h0 = *(const float4*)r0;
        float4 h1 = *(const float4*)(r0 + 128);
        float4 g0 = *(const float4*)r1;
        float4 g1 = *(const float4*)(r1 + 128);
        a0.x = fmaf(v0, h0.x, a0.x); a0.y = fmaf(v0, h0.y, a0.y);
        a0.z = fmaf(v0, h0.z, a0.z); a0.w = fmaf(v0, h0.w, a0.w);
        a1.x = fmaf(v0, h1.x, a1.x); a1.y = fmaf(v0, h1.y, a1.y);
        a1.z = fmaf(v0, h1.z, a1.z); a1.w = fmaf(v0, h1.w, a1.w);
        a0.x = fmaf(v1, g0.x, a0.x); a0.y = fmaf(v1, g0.y, a0.y);
        a0.z = fmaf(v1, g0.z, a0.z); a0.w = fmaf(v1, g0.w, a0.w);
        a1.x = fmaf(v1, g1.x, a1.x); a1.y = fmaf(v1, g1.y, a1.y);
        a1.z = fmaf(v1, g1.z, a1.z); a1.w = fmaf(v1, g1.w, a1.w);
    }
    if (p < e) {
        int c0 = g_col[p];
        float v0 = g_val[p];
        const float* r0 = src + (size_t)c0 * LD3H + lane * 4;
        float4 h0 = *(const float4*)r0;
        float4 h1 = *(const float4*)(r0 + 128);
        a0.x = fmaf(v0, h0.x, a0.x); a0.y = fmaf(v0, h0.y, a0.y);
        a0.z = fmaf(v0, h0.z, a0.z); a0.w = fmaf(v0, h0.w, a0.w);
        a1.x = fmaf(v0, h1.x, a1.x); a1.y = fmaf(v0, h1.y, a1.y);
        a1.z = fmaf(v0, h1.z, a1.z); a1.w = fmaf(v0, h1.w, a1.w);
    }
    *(float4*)(dstA + (size_t)warp * LD3H + lane * 4) = a0;
    *(float4*)(dstB + (size_t)warp * LD3H + lane * 4) = a1;
}

__global__ void k_spmm128(const float* __restrict__ src, float* __restrict__ dst)
{
    int warp = (blockIdx.x * blockDim.x + threadIdx.x) >> 5;
    int lane = threadIdx.x & 31;
    if (warp >= NN) return;
    int s = g_rowptr[warp];
    int e = g_rowptr[warp + 1];
    float4 a0 = make_float4(0.f, 0.f, 0.f, 0.f);
    int p = s;
    for (; p + 1 < e; p += 2) {
        int   c0 = g_col[p],   c1 = g_col[p + 1];
        float v0 = g_val[p],   v1 = g_val[p + 1];
        float4 h0 = *(const float4*)(src + (size_t)c0 * LD3H + lane * 4);
        float4 h1 = *(const float4*)(src + (size_t)c1 * LD3H + lane * 4);
        a0.x = fmaf(v0, h0.x, a0.x); a0.y = fmaf(v0, h0.y, a0.y);
        a0.z = fmaf(v0, h0.z, a0.z); a0.w = fmaf(v0, h0.w, a0.w);
        a0.x = fmaf(v1, h1.x, a0.x); a0.y = fmaf(v1, h1.y, a0.y);
        a0.z = fmaf(v1, h1.z, a0.z); a0.w = fmaf(v1, h1.w, a0.w);
    }
    if (p < e) {
        int c0 = g_col[p];
        float v0 = g_val[p];
        float4 h0 = *(const float4*)(src + (size_t)c0 * LD3H + lane * 4);
        a0.x = fmaf(v0, h0.x, a0.x); a0.y = fmaf(v0, h0.y, a0.y);
        a0.z = fmaf(v0, h0.z, a0.z); a0.w = fmaf(v0, h0.w, a0.w);
    }
    *(float4*)(dst + (size_t)warp * LD3H + lane * 4) = a0;
}

// ---------------- final: out = log_softmax((g + b2cat) @ wf + bf) ----------------
#define FROWS 8
__global__ __launch_bounds__(128)
void k_final(const float* __restrict__ g,
             const float* __restrict__ b2,   // [3*128]
             const float* __restrict__ wf,   // [384*16]
             const float* __restrict__ bfv,  // [16]
             float* __restrict__ out)
{
    __shared__ float wfs[LD3H * CC];
    __shared__ float gs[FROWS][LD3H];
    int tid = threadIdx.x;  // 128
    for (int i = tid; i < LD3H * CC; i += 128) wfs[i] = wf[i];
    int row0 = blockIdx.x * FROWS;
    for (int i = tid; i < FROWS * LD3H; i += 128) {
        int r = i / LD3H, k = i % LD3H;
        int gr = row0 + r;
        gs[r][k] = (gr < NN) ? g[(size_t)gr * LD3H + k] + b2[k] : 0.f;
    }
    __syncthreads();

    int r = tid >> 4;
    int c = tid & 15;
    float acc = bfv[c];
    #pragma unroll 8
    for (int k = 0; k < LD3H; k++) acc = fmaf(gs[r][k], wfs[k * CC + c], acc);

    float m = acc;
    #pragma unroll
    for (int o = 8; o >= 1; o >>= 1) m = fmaxf(m, __shfl_xor_sync(0xffffffffu, m, o, 16));
    float ex = __expf(acc - m);
    float s = ex;
    #pragma unroll
    for (int o = 8; o >= 1; o >>= 1) s += __shfl_xor_sync(0xffffffffu, s, o, 16);
    int gr = row0 + r;
    if (gr < NN) out[gr * CC + c] = acc - m - logf(s);
}

// ---------------- launch ----------------
extern "C" void kernel_launch(void* const* d_in, const int* in_sizes, int n_in,
                              void* d_out, int out_size)
{
    const float* x   = (const float*)d_in[0];
    const int*   adj = (const int*)d_in[1];
    const float* av  = (const float*)d_in[2];
    const float* w1  = (const float*)d_in[3];
    const float* b1  = (const float*)d_in[4];
    const float* w2  = (const float*)d_in[5];
    const float* b2  = (const float*)d_in[6];
    const float* wf  = (const float*)d_in[7];
    const float* bf  = (const float*)d_in[8];
    float* out = (float*)d_out;

    float *bufA, *bufB, *bufC;
    cudaGetSymbolAddress((void**)&bufA, g_bufA);
    cudaGetSymbolAddress((void**)&bufB, g_bufB);
    cudaGetSymbolAddress((void**)&bufC, g_bufC);

    cudaFuncSetAttribute(k_gemm_tc, cudaFuncAttributeMaxDynamicSharedMemorySize,
                         GEMM_SMEM_BYTES);

    const int nscan = (NN + SCAN_B - 1) / SCAN_B;  // 49

    // CSR build
    k_zero_counts<<<(NN + 255) / 256, 256>>>();
    k_count<<<(EE + 255) / 256, 256>>>(adj);
    k_scan1<<<nscan, SCAN_B>>>();
    k_scan2<<<1, 32>>>(nscan);
    k_scan3<<<nscan, SCAN_B>>>();
    k_scatter<<<(EE + 255) / 256, 256>>>(adj, av);

    dim3 ggrid(3, (NN + 127) / 128);
    const int sblocks = (NN + 3) / 4;

    // Stage 1: relu(x @ W1cat + b1cat); block0 -> bufA, blocks1,2 staged in bufB
    k_gemm_tc<<<ggrid, 256, GEMM_SMEM_BYTES>>>(x, F_IN, w1, F_IN * HH, b1,
                              bufA, bufB + HH, bufB + 2 * HH, NN, F_IN, 1);
    k_spmm256<<<sblocks, 128>>>(bufB + HH, bufA + HH, bufC + 2 * HH);
    k_spmm128<<<sblocks, 128>>>(bufC + 2 * HH, bufA + 2 * HH);

    // Stage 2: bufA @ W2cat (bias deferred); block0 -> bufC, blocks1,2 staged in bufB
    k_gemm_tc<<<ggrid, 256, GEMM_SMEM_BYTES>>>(bufA, LD3H, w2, LD3H * HH, (const float*)0,
                              bufC, bufB + HH, bufB + 2 * HH, NN, LD3H, 0);
    k_spmm256<<<sblocks, 128>>>(bufB + HH, bufC + HH, bufA + 2 * HH);
    k_spmm128<<<sblocks, 128>>>(bufA + 2 * HH, bufC + 2 * HH);

    // Final
    k_final<<<(NN + FROWS - 1) / FROWS, 128>>>(bufC, b2, wf, bf, out);

    (void)in_sizes; (void)n_in; (void)out_size;
}

// round 5
// speedup vs baseline: 1.9865x; 1.0142x over previous
#include <cuda_runtime.h>
#include <math.h>
#include <stdint.h>

// Problem constants
#define NN 50000
#define EE 800000
#define F_IN 512
#define HH 128
#define CC 16
#define LD3H 384   // 3*H

// ---------------- device scratch (static, no allocations) ----------------
__device__ int   g_count[NN];
__device__ int   g_rowptr[NN + 1];
__device__ int   g_pos[NN];
__device__ int   g_state[64];
__device__ int   g_col[EE];
__device__ float g_val[EE];
__device__ float g_bufA[(size_t)NN * LD3H];
__device__ float g_bufB[(size_t)NN * LD3H];
__device__ float g_bufC[(size_t)NN * LD3H];
__device__ float g_xr[(size_t)NN * F_IN];        // tf32-rounded copy of x
__device__ float g_w1r[3 * F_IN * HH];           // tf32-rounded w1 (same layout)
__device__ float g_w2r[3 * LD3H * HH];           // tf32-rounded w2 (same layout)

// ---------------- helpers ----------------
__device__ __forceinline__ float f2tf_f(float f) {
    uint32_t u; asm("cvt.rna.tf32.f32 %0, %1;" : "=r"(u) : "f"(f));
    return __uint_as_float(u);
}

__device__ __forceinline__ void mma_tf32(float* c, const uint32_t* a, const uint32_t* b) {
    asm volatile(
        "mma.sync.aligned.m16n8k8.row.col.f32.tf32.tf32.f32 "
        "{%0,%1,%2,%3}, {%4,%5,%6,%7}, {%8,%9}, {%0,%1,%2,%3};\n"
        : "+f"(c[0]), "+f"(c[1]), "+f"(c[2]), "+f"(c[3])
        : "r"(a[0]), "r"(a[1]), "r"(a[2]), "r"(a[3]), "r"(b[0]), "r"(b[1]));
}

__device__ __forceinline__ void cpa16(uint32_t dst_smem, const void* src, int valid) {
    asm volatile("cp.async.cg.shared.global [%0], [%1], 16, %2;\n"
                 :: "r"(dst_smem), "l"(src), "r"(valid ? 16 : 0));
}
__device__ __forceinline__ void cpa_commit() { asm volatile("cp.async.commit_group;\n"); }
__device__ __forceinline__ void cpa_wait0()  { asm volatile("cp.async.wait_group 0;\n"); }

// ---------------- fused round-to-tf32 of x, w1, w2 (float4) ----------------
#define NX4   ((size_t)NN * F_IN / 4)          // 6,400,000
#define NW14  (3 * F_IN * HH / 4)              // 49,152
#define NW24  (3 * LD3H * HH / 4)              // 36,864
__global__ void k_roundall(const float4* __restrict__ x,
                           const float4* __restrict__ w1,
                           const float4* __restrict__ w2)
{
    size_t i = (size_t)blockIdx.x * blockDim.x + threadIdx.x;
    if (i < NX4) {
        float4 v = x[i];
        v.x = f2tf_f(v.x); v.y = f2tf_f(v.y); v.z = f2tf_f(v.z); v.w = f2tf_f(v.w);
        ((float4*)g_xr)[i] = v;
    } else if (i < NX4 + NW14) {
        size_t j = i - NX4;
        float4 v = w1[j];
        v.x = f2tf_f(v.x); v.y = f2tf_f(v.y); v.z = f2tf_f(v.z); v.w = f2tf_f(v.w);
        ((float4*)g_w1r)[j] = v;
    } else if (i < NX4 + NW14 + NW24) {
        size_t j = i - NX4 - NW14;
        float4 v = w2[j];
        v.x = f2tf_f(v.x); v.y = f2tf_f(v.y); v.z = f2tf_f(v.z); v.w = f2tf_f(v.w);
        ((float4*)g_w2r)[j] = v;
    }
}

// ---------------- CSR build ----------------
__global__ void k_zero_counts() {
    int i = blockIdx.x * blockDim.x + threadIdx.x;
    if (i < NN) g_count[i] = 0;
    if (i < 64) g_state[i] = -1;
}

__global__ void k_count(const int* __restrict__ idx) {
    int e = blockIdx.x * blockDim.x + threadIdx.x;
    if (e < EE) atomicAdd(&g_count[idx[e]], 1);
}

#define SCAN_B 1024
// single-pass chained scan: 49 blocks, all co-resident
__global__ void k_scanfused() {
    __shared__ int s[SCAN_B];
    __shared__ int pfx;
    int t = threadIdx.x;
    int b = blockIdx.x;
    int i = b * SCAN_B + t;
    int v = (i < NN) ? g_count[i] : 0;
    s[t] = v;
    __syncthreads();
    #pragma unroll
    for (int o = 1; o < SCAN_B; o <<= 1) {
        int u = (t >= o) ? s[t - o] : 0;
        __syncthreads();
        s[t] += u;
        __syncthreads();
    }
    if (t == 0) {
        int total = s[SCAN_B - 1];
        int p = 0;
        if (b > 0) {
            while ((p = atomicAdd(&g_state[b - 1], 0)) < 0) {}
        }
        pfx = p;
        __threadfence();
        atomicExch(&g_state[b], p + total);
    }
    __syncthreads();
    if (i < NN) {
        int e = pfx + s[t] - v;   // exclusive
        g_rowptr[i] = e;
        g_pos[i] = e;
    }
    if (i == 0) g_rowptr[NN] = EE;
}

__global__ void k_scatter(const int* __restrict__ idx, const float* __restrict__ vals) {
    int e = blockIdx.x * blockDim.x + threadIdx.x;
    if (e < EE) {
        int r = idx[e];
        int p = atomicAdd(&g_pos[r], 1);
        g_col[p] = idx[EE + e];
        g_val[p] = vals[e];
    }
}

// ---------------- tf32 tensor-core GEMM, cp.async double-buffered ----------------
// All inputs pre-rounded to tf32 (rna) -> no cvt in mainloop.
#define LDA_S 36
#define LDB_S 136
#define A_BUF_W (128 * LDA_S)
#define B_BUF_W (32 * LDB_S)
#define GEMM_SMEM_BYTES ((2 * A_BUF_W + 2 * B_BUF_W) * 4)

__global__ __launch_bounds__(256, 2)
void k_gemm_tc(const float* __restrict__ A, int lda,
               const float* __restrict__ Bbase, int bstride,
               const float* __restrict__ bias,      // [3*128] or null
               float* __restrict__ C0, float* __restrict__ C1, float* __restrict__ C2,
               int M, int K, int do_relu, int rnd)
{
    extern __shared__ uint32_t smem[];
    uint32_t* As = smem;
    uint32_t* Bs = smem + 2 * A_BUF_W;

    const float* B = Bbase + (size_t)blockIdx.x * bstride;
    float* C = (blockIdx.x == 0) ? C0 : ((blockIdx.x == 1) ? C1 : C2);
    const float* bi = bias ? (bias + blockIdx.x * 128) : (const float*)0;

    const int m0   = blockIdx.y * 128;
    const int tid  = threadIdx.x;
    const int lane = tid & 31;
    const int wid  = tid >> 5;
    const int wm0  = (wid & 1) * 64;
    const int wn0  = (wid >> 1) * 32;
    const int gp   = lane >> 2;
    const int tg   = lane & 3;

    float acc[4][4][4];
    #pragma unroll
    for (int i = 0; i < 4; i++)
        #pragma unroll
        for (int j = 0; j < 4; j++)
            #pragma unroll
            for (int q = 0; q < 4; q++) acc[i][j][q] = 0.f;

    const int nk = K >> 5;

    auto stage = [&](int kt, int buf) {
        const int k0 = kt << 5;
        uint32_t abase = (uint32_t)__cvta_generic_to_shared(As + buf * A_BUF_W);
        uint32_t bbase = (uint32_t)__cvta_generic_to_shared(Bs + buf * B_BUF_W);
        #pragma unroll
        for (int s = 0; s < 4; s++) {
            int idx = s * 256 + tid;
            int r = idx >> 3;
            int c = (idx & 7) * 4;
            int gr = m0 + r;
            int ok = gr < M;
            int srow = ok ? gr : (M - 1);
            cpa16(abase + (r * LDA_S + c) * 4, A + (size_t)srow * lda + k0 + c, ok);
        }
        #pragma unroll
        for (int s = 0; s < 4; s++) {
            int idx = s * 256 + tid;
            int r = idx >> 5;
            int c = (idx & 31) * 4;
            cpa16(bbase + (r * LDB_S + c) * 4, B + (size_t)(k0 + r) * 128 + c, 1);
        }
        cpa_commit();
    };

    stage(0, 0);

    for (int kt = 0; kt < nk; kt++) {
        cpa_wait0();
        __syncthreads();
        if (kt + 1 < nk) stage(kt + 1, (kt + 1) & 1);

        const uint32_t* Ab = As + (kt & 1) * A_BUF_W;
        const uint32_t* Bb = Bs + (kt & 1) * B_BUF_W;

        #pragma unroll
        for (int ks = 0; ks < 4; ks++) {
            uint32_t af[4][4], bf[4][2];
            const int kk = ks * 8 + tg;
            #pragma unroll
            for (int i = 0; i < 4; i++) {
                int r = wm0 + i * 16 + gp;
                af[i][0] = Ab[r * LDA_S + kk];
                af[i][1] = Ab[(r + 8) * LDA_S + kk];
                af[i][2] = Ab[r * LDA_S + kk + 4];
                af[i][3] = Ab[(r + 8) * LDA_S + kk + 4];
            }
            #pragma unroll
            for (int j = 0; j < 4; j++) {
                int n = wn0 + j * 8 + gp;
                bf[j][0] = Bb[kk * LDB_S + n];
                bf[j][1] = Bb[(kk + 4) * LDB_S + n];
            }
            #pragma unroll
            for (int i = 0; i < 4; i++)
                #pragma unroll
                for (int j = 0; j < 4; j++)
                    mma_tf32(acc[i][j], af[i], bf[j]);
        }
        __syncthreads();
    }

    #pragma unroll
    for (int i = 0; i < 4; i++) {
        #pragma unroll
        for (int rr = 0; rr < 2; rr++) {
            int row = m0 + wm0 + i * 16 + gp + rr * 8;
            if (row >= M) continue;
            #pragma unroll
            for (int j = 0; j < 4; j++) {
                int col = wn0 + j * 8 + 2 * tg;
                float2 v;
                v.x = acc[i][j][rr * 2 + 0];
                v.y = acc[i][j][rr * 2 + 1];
                if (bi) { v.x += bi[col]; v.y += bi[col + 1]; }
                if (do_relu) { v.x = fmaxf(v.x, 0.f); v.y = fmaxf(v.y, 0.f); }
                if (rnd) { v.x = f2tf_f(v.x); v.y = f2tf_f(v.y); }
                *(float2*)(C + (size_t)row * LD3H + col) = v;
            }
        }
    }
}

// ---------------- SpMM (CSR gather) ----------------
__global__ void k_spmm256(const float* __restrict__ src,
                          float* __restrict__ dstA, float* __restrict__ dstB, int rnd)
{
    int warp = (blockIdx.x * blockDim.x + threadIdx.x) >> 5;
    int lane = threadIdx.x & 31;
    if (warp >= NN) return;
    int s = g_rowptr[warp];
    int e = g_rowptr[warp + 1];
    float4 a0 = make_float4(0.f, 0.f, 0.f, 0.f);
    float4 a1 = make_float4(0.f, 0.f, 0.f, 0.f);
    int p = s;
    for (; p + 1 < e; p += 2) {
        int   c0 = g_col[p],   c1 = g_col[p + 1];
        float v0 = g_val[p],   v1 = g_val[p + 1];
        const float* r0 = src + (size_t)c0 * LD3H + lane * 4;
        const float* r1 = src + (size_t)c1 * LD3H + lane * 4;
        float4 h0 = *(const float4*)r0;
        float4 h1 = *(const float4*)(r0 + 128);
        float4 g0 = *(const float4*)r1;
        float4 g1 = *(const float4*)(r1 + 128);
        a0.x = fmaf(v0, h0.x, a0.x); a0.y = fmaf(v0, h0.y, a0.y);
        a0.z = fmaf(v0, h0.z, a0.z); a0.w = fmaf(v0, h0.w, a0.w);
        a1.x = fmaf(v0, h1.x, a1.x); a1.y = fmaf(v0, h1.y, a1.y);
        a1.z = fmaf(v0, h1.z, a1.z); a1.w = fmaf(v0, h1.w, a1.w);
        a0.x = fmaf(v1, g0.x, a0.x); a0.y = fmaf(v1, g0.y, a0.y);
        a0.z = fmaf(v1, g0.z, a0.z); a0.w = fmaf(v1, g0.w, a0.w);
        a1.x = fmaf(v1, g1.x, a1.x); a1.y = fmaf(v1, g1.y, a1.y);
        a1.z = fmaf(v1, g1.z, a1.z); a1.w = fmaf(v1, g1.w, a1.w);
    }
    if (p < e) {
        int c0 = g_col[p];
        float v0 = g_val[p];
        const float* r0 = src + (size_t)c0 * LD3H + lane * 4;
        float4 h0 = *(const float4*)r0;
        float4 h1 = *(const float4*)(r0 + 128);
        a0.x = fmaf(v0, h0.x, a0.x); a0.y = fmaf(v0, h0.y, a0.y);
        a0.z = fmaf(v0, h0.z, a0.z); a0.w = fmaf(v0, h0.w, a0.w);
        a1.x = fmaf(v0, h1.x, a1.x); a1.y = fmaf(v0, h1.y, a1.y);
        a1.z = fmaf(v0, h1.z, a1.z); a1.w = fmaf(v0, h1.w, a1.w);
    }
    if (rnd) {
        a0.x = f2tf_f(a0.x); a0.y = f2tf_f(a0.y); a0.z = f2tf_f(a0.z); a0.w = f2tf_f(a0.w);
        a1.x = f2tf_f(a1.x); a1.y = f2tf_f(a1.y); a1.z = f2tf_f(a1.z); a1.w = f2tf_f(a1.w);
    }
    *(float4*)(dstA + (size_t)warp * LD3H + lane * 4) = a0;
    *(float4*)(dstB + (size_t)warp * LD3H + lane * 4) = a1;
}

__global__ void k_spmm128(const float* __restrict__ src, float* __restrict__ dst, int rnd)
{
    int warp = (blockIdx.x * blockDim.x + threadIdx.x) >> 5;
    int lane = threadIdx.x & 31;
    if (warp >= NN) return;
    int s = g_rowptr[warp];
    int e = g_rowptr[warp + 1];
    float4 a0 = make_float4(0.f, 0.f, 0.f, 0.f);
    int p = s;
    for (; p + 1 < e; p += 2) {
        int   c0 = g_col[p],   c1 = g_col[p + 1];
        float v0 = g_val[p],   v1 = g_val[p + 1];
        float4 h0 = *(const float4*)(src + (size_t)c0 * LD3H + lane * 4);
        float4 h1 = *(const float4*)(src + (size_t)c1 * LD3H + lane * 4);
        a0.x = fmaf(v0, h0.x, a0.x); a0.y = fmaf(v0, h0.y, a0.y);
        a0.z = fmaf(v0, h0.z, a0.z); a0.w = fmaf(v0, h0.w, a0.w);
        a0.x = fmaf(v1, h1.x, a0.x); a0.y = fmaf(v1, h1.y, a0.y);
        a0.z = fmaf(v1, h1.z, a0.z); a0.w = fmaf(v1, h1.w, a0.w);
    }
    if (p < e) {
        int c0 = g_col[p];
        float v0 = g_val[p];
        float4 h0 = *(const float4*)(src + (size_t)c0 * LD3H + lane * 4);
        a0.x = fmaf(v0, h0.x, a0.x); a0.y = fmaf(v0, h0.y, a0.y);
        a0.z = fmaf(v0, h0.z, a0.z); a0.w = fmaf(v0, h0.w, a0.w);
    }
    if (rnd) {
        a0.x = f2tf_f(a0.x); a0.y = f2tf_f(a0.y); a0.z = f2tf_f(a0.z); a0.w = f2tf_f(a0.w);
    }
    *(float4*)(dst + (size_t)warp * LD3H + lane * 4) = a0;
}

// ---------------- final: out = log_softmax((g + b2cat) @ wf + bf) ----------------
#define FROWS 8
__global__ __launch_bounds__(128)
void k_final(const float* __restrict__ g,
             const float* __restrict__ b2,
             const float* __restrict__ wf,
             const float* __restrict__ bfv,
             float* __restrict__ out)
{
    __shared__ float wfs[LD3H * CC];
    __shared__ float gs[FROWS][LD3H];
    int tid = threadIdx.x;
    for (int i = tid; i < LD3H * CC; i += 128) wfs[i] = wf[i];
    int row0 = blockIdx.x * FROWS;
    for (int i = tid; i < FROWS * LD3H; i += 128) {
        int r = i / LD3H, k = i % LD3H;
        int gr = row0 + r;
        gs[r][k] = (gr < NN) ? g[(size_t)gr * LD3H + k] + b2[k] : 0.f;
    }
    __syncthreads();

    int r = tid >> 4;
    int c = tid & 15;
    float acc = bfv[c];
    #pragma unroll 8
    for (int k = 0; k < LD3H; k++) acc = fmaf(gs[r][k], wfs[k * CC + c], acc);

    float m = acc;
    #pragma unroll
    for (int o = 8; o >= 1; o >>= 1) m = fmaxf(m, __shfl_xor_sync(0xffffffffu, m, o, 16));
    float ex = __expf(acc - m);
    float s = ex;
    #pragma unroll
    for (int o = 8; o >= 1; o >>= 1) s += __shfl_xor_sync(0xffffffffu, s, o, 16);
    int gr = row0 + r;
    if (gr < NN) out[gr * CC + c] = acc - m - logf(s);
}

// ---------------- launch ----------------
extern "C" void kernel_launch(void* const* d_in, const int* in_sizes, int n_in,
                              void* d_out, int out_size)
{
    const float* x   = (const float*)d_in[0];
    const int*   adj = (const int*)d_in[1];
    const float* av  = (const float*)d_in[2];
    const float* w1  = (const float*)d_in[3];
    const float* b1  = (const float*)d_in[4];
    const float* w2  = (const float*)d_in[5];
    const float* b2  = (const float*)d_in[6];
    const float* wf  = (const float*)d_in[7];
    const float* bf  = (const float*)d_in[8];
    float* out = (float*)d_out;

    float *bufA, *bufB, *bufC, *xr, *w1r, *w2r;
    cudaGetSymbolAddress((void**)&bufA, g_bufA);
    cudaGetSymbolAddress((void**)&bufB, g_bufB);
    cudaGetSymbolAddress((void**)&bufC, g_bufC);
    cudaGetSymbolAddress((void**)&xr,   g_xr);
    cudaGetSymbolAddress((void**)&w1r,  g_w1r);
    cudaGetSymbolAddress((void**)&w2r,  g_w2r);

    cudaFuncSetAttribute(k_gemm_tc, cudaFuncAttributeMaxDynamicSharedMemorySize,
                         GEMM_SMEM_BYTES);

    // persistent side stream + fork/join events (created once, on the
    // correctness call, i.e. outside graph capture)
    static cudaStream_t s2 = 0;
    static cudaEvent_t evFork = 0, evJoin = 0;
    if (!s2) {
        cudaStreamCreateWithFlags(&s2, cudaStreamNonBlocking);
        cudaEventCreateWithFlags(&evFork, cudaEventDisableTiming);
        cudaEventCreateWithFlags(&evJoin, cudaEventDisableTiming);
    }

    const int nscan = (NN + SCAN_B - 1) / SCAN_B;  // 49

    // ---- fork: CSR build on s2, GEMM path on default stream ----
    cudaEventRecord(evFork, 0);
    cudaStreamWaitEvent(s2, evFork, 0);

    k_zero_counts<<<(NN + 255) / 256, 256, 0, s2>>>();
    k_count<<<(EE + 255) / 256, 256, 0, s2>>>(adj);
    k_scanfused<<<nscan, SCAN_B, 0, s2>>>();
    k_scatter<<<(EE + 255) / 256, 256, 0, s2>>>(adj, av);
    cudaEventRecord(evJoin, s2);

    // default stream: pre-round inputs + GEMM1
    const size_t ntot4 = NX4 + NW14 + NW24;
    k_roundall<<<(unsigned)((ntot4 + 255) / 256), 256>>>(
        (const float4*)x, (const float4*)w1, (const float4*)w2);

    dim3 ggrid(3, (NN + 127) / 128);
    k_gemm_tc<<<ggrid, 256, GEMM_SMEM_BYTES>>>(xr, F_IN, w1r, F_IN * HH, b1,
                              bufA, bufB + HH, bufB + 2 * HH, NN, F_IN, 1, 1);

    // ---- join: spmm needs CSR ----
    cudaStreamWaitEvent(0, evJoin, 0);

    const int sblocks = (NN + 3) / 4;
    k_spmm256<<<sblocks, 128>>>(bufB + HH, bufA + HH, bufC + 2 * HH, 1);
    k_spmm128<<<sblocks, 128>>>(bufC + 2 * HH, bufA + 2 * HH, 1);

    k_gemm_tc<<<ggrid, 256, GEMM_SMEM_BYTES>>>(bufA, LD3H, w2r, LD3H * HH, (const float*)0,
                              bufC, bufB + HH, bufB + 2 * HH, NN, LD3H, 0, 0);
    k_spmm256<<<sblocks, 128>>>(bufB + HH, bufC + HH, bufA + 2 * HH, 0);
    k_spmm128<<<sblocks, 128>>>(bufA + 2 * HH, bufC + 2 * HH, 0);

    k_final<<<(NN + FROWS - 1) / FROWS, 128>>>(bufC, b2, wf, bf, out);

    (void)in_sizes; (void)n_in; (void)out_size;
}